// round 7
// baseline (speedup 1.0000x reference)
#include <cuda_runtime.h>
#include <math_constants.h>

#define NCLS   20
#define NBOX   400
#define SORTN  512
#define IMGW   1333.0f
#define IMGH   800.0f
#define TOPK   100
#define NSEL   (NCLS * TOPK)     // 2000
#define NW     13                // 400 bits -> 13 u32 words
#define SENTK  0xFFFFFFFFFFFFFFFFull
#define FULLM  0xFFFFFFFFu
#define NTHR   1024

// ---------------- device scratch (counters reset by last finisher each replay) ------
__device__ unsigned long long g_selkey[NSEL];
__device__ unsigned int       g_maxBits = 0u;
__device__ unsigned int       g_maxCnt  = 0u;
__device__ unsigned int       g_T       = 0u;
__device__ unsigned int       g_done    = 0u;
__device__ unsigned int       g_done2   = 0u;

// descending-sortable mapping (ascending u64 sort -> descending float score)
__device__ __forceinline__ unsigned int ord_desc(float f) {
    unsigned int u = __float_as_uint(f);
    unsigned int m = (u & 0x80000000u) ? ~u : (u | 0x80000000u);
    return ~m;
}
__device__ __forceinline__ float inv_ord(unsigned int o) {
    unsigned int m = ~o;
    unsigned int u = (m & 0x80000000u) ? (m & 0x7FFFFFFFu) : ~m;
    return __uint_as_float(u);
}
__device__ __forceinline__ unsigned long long shfl_xor_u64(unsigned long long v, int jj) {
    unsigned int lo = (unsigned int)v, hi = (unsigned int)(v >> 32);
    lo = __shfl_xor_sync(FULLM, lo, jj);
    hi = __shfl_xor_sync(FULLM, hi, jj);
    return ((unsigned long long)hi << 32) | lo;
}
__device__ __forceinline__ unsigned long long uminll(unsigned long long a, unsigned long long b) { return a < b ? a : b; }
__device__ __forceinline__ unsigned long long umaxll(unsigned long long a, unsigned long long b) { return a > b ? a : b; }

__global__ void __launch_bounds__(NTHR, 1)
k_all(const float* __restrict__ boxes, const float* __restrict__ scores,
      const int* __restrict__ pred_cls, float* __restrict__ out)
{
    // union: cbox (6.4KB, A-D) -> mask (20.8KB, E-F) -> sel (16KB, merge)
    __shared__ __align__(16) unsigned char u_raw[NBOX * NW * 4];   // 20800 B
    __shared__ __align__(16) unsigned long long skey[SORTN];       // 4 KB
    __shared__ __align__(16) float4 s_b[NBOX];                     // 6.4 KB shifted boxes
    __shared__ float        s_a[NBOX];                             // 1.6 KB areas
    __shared__ unsigned int s_wmax[32];
    __shared__ float        s_shift;
    __shared__ int          s_T;

    float4*             s_cbox = reinterpret_cast<float4*>(u_raw);
    unsigned int*       s_mask = reinterpret_cast<unsigned int*>(u_raw);
    unsigned long long* s_sel  = reinterpret_cast<unsigned long long*>(u_raw);

    const int c    = blockIdx.x;               // class, one block per class
    const int tid  = threadIdx.x;
    const int lane = tid & 31;

    // ---------- phase A: load class, clip, keys, local max ----------
    float lmax = 0.0f;
    bool  valid = false;
    unsigned long long v = SENTK;
    if (tid < NBOX) {
        float4 bx = reinterpret_cast<const float4*>(boxes)[c * NBOX + tid];
        float2 sc = reinterpret_cast<const float2*>(scores)[c * NBOX + tid];
        bool fin = isfinite(bx.x) && isfinite(bx.y) && isfinite(bx.z) && isfinite(bx.w)
                && isfinite(sc.x) && isfinite(sc.y);
        float x1 = fminf(fmaxf(bx.x, 0.0f), IMGW);
        float y1 = fminf(fmaxf(bx.y, 0.0f), IMGH);
        float x2 = fminf(fmaxf(bx.z, 0.0f), IMGW);
        float y2 = fminf(fmaxf(bx.w, 0.0f), IMGH);
        valid = fin && (sc.x > 0.05f);
        float masked = valid ? sc.x : -CUDART_INF_F;
        unsigned int j = (unsigned int)(tid * NCLS + c);   // transposed index
        v = ((unsigned long long)ord_desc(masked) << 32) | j;
        s_cbox[tid] = make_float4(x1, y1, x2, y2);
        lmax = fmaxf(fmaxf(x1, x2), fmaxf(y1, y2));
    }
    unsigned int wb = __reduce_max_sync(FULLM, __float_as_uint(lmax));
    if (lane == 0) s_wmax[tid >> 5] = wb;
    const int m = __syncthreads_count(valid);
    if (tid == 0) {                            // one publisher per class
        unsigned int mx = 0;
        #pragma unroll
        for (int w = 0; w < 32; w++) mx = max(mx, s_wmax[w]);
        atomicMax(&g_maxBits, mx);
        __threadfence();
        atomicAdd(&g_maxCnt, 1u);
    }

    // ---------- phase B: hybrid bitonic sort of 512 keys (threads < 512; hides rendezvous) ----------
    for (int k = 2; k <= SORTN; k <<= 1) {
        for (int jj = k >> 1; jj >= 32; jj >>= 1) {
            if (tid < SORTN) skey[tid] = v;
            __syncthreads();
            if (tid < SORTN) {
                unsigned long long p = skey[tid ^ jj];
                bool km = (((tid & k) == 0) == ((tid & jj) == 0));
                v = km ? uminll(v, p) : umaxll(v, p);
            }
            __syncthreads();
        }
        if (tid < SORTN) {
            int j0 = (k >> 1) < 16 ? (k >> 1) : 16;
            for (int jj = j0; jj >= 1; jj >>= 1) {
                unsigned long long p = shfl_xor_u64(v, jj);
                bool km = (((tid & k) == 0) == ((tid & jj) == 0));
                v = km ? uminll(v, p) : umaxll(v, p);
            }
        }
    }
    if (tid < SORTN) skey[tid] = v;            // sorted keys in smem

    // ---------- phase C: wait for global max, compute shift ----------
    if (tid == 0) {
        volatile unsigned int* vc = &g_maxCnt;
        while (*vc < (unsigned)NCLS) { }
        __threadfence();
        unsigned int mv = *(volatile unsigned int*)&g_maxBits;
        s_shift = __fmul_rn((float)c, __fadd_rn(__uint_as_float(mv), 1.0f));
    }
    __syncthreads();

    // ---------- phase D: shifted boxes + areas in sorted order ----------
    const float shift = s_shift;
    if (tid < m) {
        unsigned int j = (unsigned int)skey[tid];
        int b = (int)(j / NCLS);
        float4 bx = s_cbox[b];
        float4 sb = make_float4(__fadd_rn(bx.x, shift), __fadd_rn(bx.y, shift),
                                __fadd_rn(bx.z, shift), __fadd_rn(bx.w, shift));
        s_b[tid] = sb;
        s_a[tid] = __fmul_rn(__fsub_rn(sb.z, sb.x), __fsub_rn(sb.w, sb.y));
    }
    __syncthreads();                           // s_cbox dead; s_mask alias live next

    // ---------- phase E: full mask matrix in smem ----------
    const int total = m * NW;
    for (int lin = tid; lin < total; lin += NTHR) {
        int i = lin / NW;
        int w = lin - i * NW;
        unsigned int bits = 0;
        const int lo = w * 32;
        const int hi = min(m, lo + 32);
        const int st = max(lo, i + 1);
        if (st < hi) {
            float4 bi = s_b[i];
            float  ai = s_a[i];
            for (int jd = st; jd < hi; jd++) {
                float4 bj = s_b[jd];
                float iw = fmaxf(__fsub_rn(fminf(bi.z, bj.z), fmaxf(bi.x, bj.x)), 0.0f);
                float ih = fmaxf(__fsub_rn(fminf(bi.w, bj.w), fmaxf(bi.y, bj.y)), 0.0f);
                float inter = __fmul_rn(iw, ih);
                float uni = __fsub_rn(__fadd_rn(ai, s_a[jd]), inter);
                float iou = (uni > 0.0f) ? __fdiv_rn(inter, uni) : 0.0f;
                if (iou > 0.5f) bits |= 1u << (jd - lo);
            }
        }
        s_mask[i * NW + w] = bits;
    }
    __syncthreads();

    // ---------- phase F: greedy scan (warp 0, register-batched) + emit kept top-100 ----------
    if (tid < 32) {
        unsigned int mysup = 0;                // lane w owns rows [32w, 32w+32)
        const int nb = (m + 31) >> 5;
        for (int b = 0; b < nb; b++) {
            unsigned int cur = __shfl_sync(FULLM, mysup, b);
            const int base = b << 5;
            const int rows = min(32, m - base);
            unsigned int wreg[32];
            #pragma unroll
            for (int q = 0; q < 32; q++)
                wreg[q] = (q < rows) ? s_mask[(base + q) * NW + b] : 0u;
            #pragma unroll
            for (int q = 0; q < 32; q++) {
                if (q < rows && !((cur >> q) & 1u)) {
                    cur |= wreg[q];
                    if (lane < NW) mysup |= s_mask[(base + q) * NW + lane];
                }
            }
        }
        int cnt = 0;
        for (int bs = 0; bs < m; bs += 32) {
            int t = bs + lane;
            unsigned int supw = __shfl_sync(FULLM, mysup, t >> 5);
            bool kept = (t < m) && !((supw >> (t & 31)) & 1u);
            unsigned int bal = __ballot_sync(FULLM, kept);
            int pos = cnt + __popc(bal & ((1u << lane) - 1u));
            if (kept && pos < TOPK) g_selkey[c * TOPK + pos] = skey[t];
            cnt += __popc(bal);
        }
        cnt = min(cnt, TOPK);
        for (int p = cnt + lane; p < TOPK; p += 32) g_selkey[c * TOPK + p] = SENTK;
        __threadfence();                       // each lane publishes its stores
        __syncwarp();
        if (lane == 0) {
            atomicAdd(&g_T, (unsigned int)cnt);
            __threadfence();
            atomicAdd(&g_done, 1u);
        }
    }
    __syncthreads();

    // ---------- rendezvous: all 20 classes' selkey visible ----------
    if (tid == 0) {
        volatile unsigned int* vd = &g_done;
        while (*vd < (unsigned)NCLS) { }
        __threadfence();
        s_T = (int)*(volatile unsigned int*)&g_T;
    }
    __syncthreads();                           // s_mask dead; s_sel alias live next

    for (int t = tid; t < NSEL; t += NTHR) s_sel[t] = g_selkey[t];
    __syncthreads();

    // block 0 fills default rows [T, 100)
    if (c == 0) {
        for (int r = s_T + tid; r < TOPK; r += NTHR) {
            out[r * 4 + 0] = 0.0f;
            out[r * 4 + 1] = 0.0f;
            out[r * 4 + 2] = 0.0f;
            out[r * 4 + 3] = 0.0f;
            out[4 * TOPK + r] = 0.0f;
            out[5 * TOPK + r] = -1.0f;
            out[6 * TOPK + r] = 0.0f;
        }
    }

    // merge-by-rank: rank own class's kept keys against the other 19 sorted lists
    if (tid < TOPK) {
        unsigned long long e = s_sel[c * TOPK + tid];
        if (e != SENTK) {
            int rank = tid;                    // position within own sorted list
            #pragma unroll
            for (int c2 = 0; c2 < NCLS; c2++) {
                if (c2 == c) continue;
                const unsigned long long* seg = s_sel + c2 * TOPK;
                int lo = 0;                    // lower_bound: #elements < e
                #pragma unroll
                for (int s = 64; s > 0; s >>= 1) {
                    int p = lo + s;
                    if (p <= TOPK && seg[p - 1] < e) lo = p;
                }
                rank += lo;
            }
            if (rank < TOPK) {
                unsigned int j = (unsigned int)e;
                int cc = (int)(j % NCLS);
                int b  = (int)(j / NCLS);
                int i  = cc * NBOX + b;
                float4 bx = reinterpret_cast<const float4*>(boxes)[i];
                out[rank * 4 + 0] = fminf(fmaxf(bx.x, 0.0f), IMGW);
                out[rank * 4 + 1] = fminf(fmaxf(bx.y, 0.0f), IMGH);
                out[rank * 4 + 2] = fminf(fmaxf(bx.z, 0.0f), IMGW);
                out[rank * 4 + 3] = fminf(fmaxf(bx.w, 0.0f), IMGH);
                out[4 * TOPK + rank] = inv_ord((unsigned int)(e >> 32));
                out[5 * TOPK + rank] = (float)pred_cls[i];
                out[6 * TOPK + rank] = 1.0f;
            }
        }
    }

    // ---------- last finisher resets counters for next graph replay ----------
    __syncthreads();
    if (tid == 0) {
        unsigned int r2 = atomicAdd(&g_done2, 1u);
        if (r2 == NCLS - 1) {
            g_maxBits = 0u;
            g_maxCnt  = 0u;
            g_T       = 0u;
            g_done    = 0u;
            g_done2   = 0u;
            __threadfence();
        }
    }
}

// ---------------- launch ----------------
extern "C" void kernel_launch(void* const* d_in, const int* in_sizes, int n_in,
                              void* d_out, int out_size) {
    const int*   pred_cls = (const int*)d_in[0];
    const float* boxes    = (const float*)d_in[1];
    const float* scores   = (const float*)d_in[2];
    float* out = (float*)d_out;

    k_all<<<NCLS, NTHR>>>(boxes, scores, pred_cls, out);
}

// round 9
// speedup vs baseline: 2.2593x; 2.2593x over previous
#include <cuda_runtime.h>
#include <math_constants.h>

#define NCLS   20
#define NBOX   400
#define SORTN  512
#define IMGW   1333.0f
#define IMGH   800.0f
#define TOPK   100
#define NSEL   (NCLS * TOPK)     // 2000
#define NW     13                // 400 bits -> 13 u32 words
#define SENTK  0xFFFFFFFFFFFFFFFFull
#define FULLM  0xFFFFFFFFu

// ---------------- device scratch ----------------
__device__ unsigned long long g_skey[NCLS * SORTN];   // sorted keys per class
__device__ float4             g_sbox[NCLS * NBOX];    // clipped boxes in sorted order
__device__ int                g_m[NCLS];              // valid count per class
__device__ unsigned int       g_mask[NCLS * NBOX * NW];
__device__ unsigned long long g_selkey[NSEL];         // per class: sorted kept top-100 (pad)
__device__ unsigned int       g_maxBits = 0u;
__device__ unsigned int       g_T       = 0u;
__device__ unsigned int       g_done    = 0u;
__device__ unsigned int       g_done2   = 0u;

// descending-sortable mapping (ascending u64 sort -> descending float score)
__device__ __forceinline__ unsigned int ord_desc(float f) {
    unsigned int u = __float_as_uint(f);
    unsigned int m = (u & 0x80000000u) ? ~u : (u | 0x80000000u);
    return ~m;
}
__device__ __forceinline__ float inv_ord(unsigned int o) {
    unsigned int m = ~o;
    unsigned int u = (m & 0x80000000u) ? (m & 0x7FFFFFFFu) : ~m;
    return __uint_as_float(u);
}
__device__ __forceinline__ unsigned long long shfl_xor_u64(unsigned long long v, int jj) {
    unsigned int lo = (unsigned int)v, hi = (unsigned int)(v >> 32);
    lo = __shfl_xor_sync(FULLM, lo, jj);
    hi = __shfl_xor_sync(FULLM, hi, jj);
    return ((unsigned long long)hi << 32) | lo;
}
__device__ __forceinline__ unsigned long long uminll(unsigned long long a, unsigned long long b) { return a < b ? a : b; }
__device__ __forceinline__ unsigned long long umaxll(unsigned long long a, unsigned long long b) { return a > b ? a : b; }

// ---------------- k1: per-class load/clip/key + hybrid bitonic sort ----------------
__global__ void __launch_bounds__(SORTN) k1(const float* __restrict__ boxes,
                                            const float* __restrict__ scores) {
    __shared__ unsigned long long skey[SORTN];
    __shared__ float4       s_cbox[NBOX];
    __shared__ unsigned int s_wmax[16];

    const int cls = blockIdx.x, tid = threadIdx.x, lane = tid & 31;

    float lmax = 0.0f;
    bool  valid = false;
    unsigned long long v = SENTK;
    if (tid < NBOX) {
        float4 bx = reinterpret_cast<const float4*>(boxes)[cls * NBOX + tid];
        float2 sc = reinterpret_cast<const float2*>(scores)[cls * NBOX + tid];
        bool fin = isfinite(bx.x) && isfinite(bx.y) && isfinite(bx.z) && isfinite(bx.w)
                && isfinite(sc.x) && isfinite(sc.y);
        float x1 = fminf(fmaxf(bx.x, 0.0f), IMGW);
        float y1 = fminf(fmaxf(bx.y, 0.0f), IMGH);
        float x2 = fminf(fmaxf(bx.z, 0.0f), IMGW);
        float y2 = fminf(fmaxf(bx.w, 0.0f), IMGH);
        valid = fin && (sc.x > 0.05f);
        float masked = valid ? sc.x : -CUDART_INF_F;
        unsigned int j = (unsigned int)(tid * NCLS + cls);       // transposed index
        v = ((unsigned long long)ord_desc(masked) << 32) | j;
        s_cbox[tid] = make_float4(x1, y1, x2, y2);
        lmax = fmaxf(fmaxf(x1, x2), fmaxf(y1, y2));
    }
    unsigned int wb = __reduce_max_sync(FULLM, __float_as_uint(lmax));
    if (lane == 0) s_wmax[tid >> 5] = wb;
    const int m = __syncthreads_count(valid);
    if (tid == 0) {
        unsigned int mx = 0;
        #pragma unroll
        for (int w = 0; w < 16; w++) mx = max(mx, s_wmax[w]);
        atomicMax(&g_maxBits, mx);
    }

    // hybrid bitonic sort: smem stages jj>=32, shfl stages jj<=16
    for (int k = 2; k <= SORTN; k <<= 1) {
        for (int jj = k >> 1; jj >= 32; jj >>= 1) {
            skey[tid] = v;
            __syncthreads();
            unsigned long long p = skey[tid ^ jj];
            bool km = (((tid & k) == 0) == ((tid & jj) == 0));
            v = km ? uminll(v, p) : umaxll(v, p);
            __syncthreads();
        }
        int j0 = (k >> 1) < 16 ? (k >> 1) : 16;
        for (int jj = j0; jj >= 1; jj >>= 1) {
            unsigned long long p = shfl_xor_u64(v, jj);
            bool km = (((tid & k) == 0) == ((tid & jj) == 0));
            v = km ? uminll(v, p) : umaxll(v, p);
        }
    }

    g_skey[cls * SORTN + tid] = v;
    if (tid < m) {
        unsigned int j = (unsigned int)v;
        int b = (int)(j / NCLS);
        g_sbox[cls * NBOX + tid] = s_cbox[b];
    }
    if (tid == 0) g_m[cls] = m;
}

// ---------------- k2: mask matrix, 260 blocks (class x 32-row tile) ----------------
__global__ void __launch_bounds__(416) k2() {
    __shared__ float4 s_b[NBOX];
    __shared__ float  s_a[NBOX];

    const int c = blockIdx.y, ty = blockIdx.x;
    const int tid = threadIdx.x;
    const int wd = tid >> 5, lane = tid & 31;
    const int m = g_m[c];

    const float offv  = __fadd_rn(__uint_as_float(g_maxBits), 1.0f);
    const float shift = __fmul_rn((float)c, offv);

    for (int t = tid; t < m; t += 416) {
        float4 bx = g_sbox[c * NBOX + t];
        float4 sb = make_float4(__fadd_rn(bx.x, shift), __fadd_rn(bx.y, shift),
                                __fadd_rn(bx.z, shift), __fadd_rn(bx.w, shift));
        s_b[t] = sb;
        s_a[t] = __fmul_rn(__fsub_rn(sb.z, sb.x), __fsub_rn(sb.w, sb.y));
    }
    __syncthreads();

    const int i = ty * 32 + lane;
    if (i >= m) return;

    unsigned int bits = 0;
    const int lo = wd * 32;
    const int hi = min(m, lo + 32);
    const int st = max(lo, i + 1);
    if (st < hi) {
        float4 bi = s_b[i];
        float  ai = s_a[i];
        for (int jd = st; jd < hi; jd++) {
            float4 bj = s_b[jd];
            float iw = fmaxf(__fsub_rn(fminf(bi.z, bj.z), fmaxf(bi.x, bj.x)), 0.0f);
            float ih = fmaxf(__fsub_rn(fminf(bi.w, bj.w), fmaxf(bi.y, bj.y)), 0.0f);
            float inter = __fmul_rn(iw, ih);
            float uni = __fsub_rn(__fadd_rn(ai, s_a[jd]), inter);
            float iou = (uni > 0.0f) ? __fdiv_rn(inter, uni) : 0.0f;
            if (iou > 0.5f) bits |= 1u << (jd - lo);
        }
    }
    g_mask[(c * NBOX + i) * NW + wd] = bits;
}

// ---------------- k34: greedy scan + rendezvous + merge-by-rank + output ----------------
__global__ void __launch_bounds__(512) k34(const float* __restrict__ boxes,
                                           const int* __restrict__ pred_cls,
                                           float* __restrict__ out) {
    __shared__ __align__(16) unsigned int       s_mask[NBOX * NW];  // 20.8 KB
    __shared__ __align__(16) unsigned long long s_sel[NSEL];        // 16 KB
    __shared__ unsigned long long s_skey[SORTN];                    // 4 KB
    __shared__ int s_T;

    const int c = blockIdx.x, tid = threadIdx.x, lane = tid & 31;
    const int m = g_m[c];

    // stage mask + own sorted keys into smem (512 threads, high MLP)
    for (int t = tid; t < m * NW; t += 512) s_mask[t] = g_mask[c * NBOX * NW + t];
    for (int t = tid; t < SORTN; t += 512)  s_skey[t] = g_skey[c * SORTN + t];
    __syncthreads();

    // greedy scan (warp 0, register-batched) + emit kept top-100 to global
    if (tid < 32) {
        unsigned int mysup = 0;                // lane w owns rows [32w, 32w+32)
        const int nb = (m + 31) >> 5;
        for (int b = 0; b < nb; b++) {
            unsigned int cur = __shfl_sync(FULLM, mysup, b);
            const int base = b << 5;
            const int rows = min(32, m - base);
            unsigned int wreg[32];
            #pragma unroll
            for (int q = 0; q < 32; q++)
                wreg[q] = (q < rows) ? s_mask[(base + q) * NW + b] : 0u;
            #pragma unroll
            for (int q = 0; q < 32; q++) {
                if (q < rows && !((cur >> q) & 1u)) {
                    cur |= wreg[q];
                    if (lane < NW) mysup |= s_mask[(base + q) * NW + lane];
                }
            }
        }
        int cnt = 0;
        for (int bs = 0; bs < m; bs += 32) {
            int t = bs + lane;
            unsigned int supw = __shfl_sync(FULLM, mysup, t >> 5);
            bool kept = (t < m) && !((supw >> (t & 31)) & 1u);
            unsigned int bal = __ballot_sync(FULLM, kept);
            int pos = cnt + __popc(bal & ((1u << lane) - 1u));
            if (kept && pos < TOPK) g_selkey[c * TOPK + pos] = s_skey[t];
            cnt += __popc(bal);
        }
        cnt = min(cnt, TOPK);
        for (int p = cnt + lane; p < TOPK; p += 32) g_selkey[c * TOPK + p] = SENTK;
        __threadfence();                       // publish selkey stores
        __syncwarp();
        if (lane == 0) {
            atomicAdd(&g_T, (unsigned int)cnt);
            __threadfence();
            atomicAdd(&g_done, 1u);
        }
    }
    __syncthreads();

    // rendezvous: all 20 classes' selkey visible (blocks run identical code -> tiny skew)
    if (tid == 0) {
        volatile unsigned int* vd = &g_done;
        while (*vd < (unsigned)NCLS) { }
        __threadfence();
        s_T = (int)*(volatile unsigned int*)&g_T;
    }
    __syncthreads();

    // load all 2000 candidates (512 threads -> 4 loads each, high MLP)
    for (int t = tid; t < NSEL; t += 512) s_sel[t] = g_selkey[t];
    __syncthreads();

    // block 0 fills default rows [T, 100)
    if (c == 0) {
        for (int r = s_T + tid; r < TOPK; r += 512) {
            out[r * 4 + 0] = 0.0f;
            out[r * 4 + 1] = 0.0f;
            out[r * 4 + 2] = 0.0f;
            out[r * 4 + 3] = 0.0f;
            out[4 * TOPK + r] = 0.0f;
            out[5 * TOPK + r] = -1.0f;
            out[6 * TOPK + r] = 0.0f;
        }
    }

    // merge-by-rank: rank own class's kept keys against the other 19 sorted lists
    if (tid < TOPK) {
        unsigned long long e = s_sel[c * TOPK + tid];
        if (e != SENTK) {
            int rank = tid;                    // position within own sorted list
            #pragma unroll
            for (int c2 = 0; c2 < NCLS; c2++) {
                if (c2 == c) continue;
                const unsigned long long* seg = s_sel + c2 * TOPK;
                int lo = 0;                    // lower_bound: #elements < e
                #pragma unroll
                for (int s = 64; s > 0; s >>= 1) {
                    int p = lo + s;
                    if (p <= TOPK && seg[p - 1] < e) lo = p;
                }
                rank += lo;
            }
            if (rank < TOPK) {
                unsigned int j = (unsigned int)e;
                int cc = (int)(j % NCLS);
                int b  = (int)(j / NCLS);
                int i  = cc * NBOX + b;
                float4 bx = reinterpret_cast<const float4*>(boxes)[i];
                out[rank * 4 + 0] = fminf(fmaxf(bx.x, 0.0f), IMGW);
                out[rank * 4 + 1] = fminf(fmaxf(bx.y, 0.0f), IMGH);
                out[rank * 4 + 2] = fminf(fmaxf(bx.z, 0.0f), IMGW);
                out[rank * 4 + 3] = fminf(fmaxf(bx.w, 0.0f), IMGH);
                out[4 * TOPK + rank] = inv_ord((unsigned int)(e >> 32));
                out[5 * TOPK + rank] = (float)pred_cls[i];
                out[6 * TOPK + rank] = 1.0f;
            }
        }
    }

    // last finisher resets globals for the next graph replay
    __syncthreads();
    if (tid == 0) {
        unsigned int r2 = atomicAdd(&g_done2, 1u);
        if (r2 == NCLS - 1) {
            g_maxBits = 0u;
            g_T       = 0u;
            g_done    = 0u;
            g_done2   = 0u;
            __threadfence();
        }
    }
}

// ---------------- launch ----------------
extern "C" void kernel_launch(void* const* d_in, const int* in_sizes, int n_in,
                              void* d_out, int out_size) {
    const int*   pred_cls = (const int*)d_in[0];
    const float* boxes    = (const float*)d_in[1];
    const float* scores   = (const float*)d_in[2];
    float* out = (float*)d_out;

    k1<<<NCLS, SORTN>>>(boxes, scores);
    k2<<<dim3(13, NCLS), 416>>>();
    k34<<<NCLS, 512>>>(boxes, pred_cls, out);
}